// round 3
// baseline (speedup 1.0000x reference)
#include <cuda_runtime.h>
#include <math.h>

#define HIDDEN 1024
#define NINTER 256
#define WINDOW 64

// scratch (allocation-free rule: __device__ global)
__device__ float g_p[NINTER];

// ---------------------------------------------------------------------------
// Kernel 1: g_p[row] = tanh(dot(fc1_w[row,:], h_t) + fc1_b[row])
// Warp-per-row: 32 blocks x 256 threads (8 warps = 8 rows per block).
// Each lane: 8 float4 of w + 8 float4 of h = 16 independent loads (one
// DRAM-latency batch), 4 fp64 accumulators, warp shuffle reduce, fp64 tanh.
// ---------------------------------------------------------------------------
__global__ void __launch_bounds__(256) mlp1_kernel(
        const float* __restrict__ ht,
        const float* __restrict__ fc1_w,
        const float* __restrict__ fc1_b) {
    const int lane = threadIdx.x & 31;
    const int wid  = threadIdx.x >> 5;
    const int row  = (blockIdx.x << 3) + wid;

    const float4* wp = (const float4*)(fc1_w + (size_t)row * HIDDEN);
    const float4* hp = (const float4*)ht;

    float4 w[8], h[8];
    #pragma unroll
    for (int j = 0; j < 8; j++) { w[j] = wp[lane + (j << 5)]; }
    #pragma unroll
    for (int j = 0; j < 8; j++) { h[j] = hp[lane + (j << 5)]; }

    double a0 = 0.0, a1 = 0.0, a2 = 0.0, a3 = 0.0;
    #pragma unroll
    for (int j = 0; j < 8; j++) {
        a0 += (double)w[j].x * h[j].x;
        a1 += (double)w[j].y * h[j].y;
        a2 += (double)w[j].z * h[j].z;
        a3 += (double)w[j].w * h[j].w;
    }
    double acc = (a0 + a1) + (a2 + a3);
    #pragma unroll
    for (int o = 16; o > 0; o >>= 1)
        acc += __shfl_down_sync(0xffffffffu, acc, o);

    if (lane == 0)
        g_p[row] = (float)tanh(acc + (double)fc1_b[row]);
}

// ---------------------------------------------------------------------------
// Kernel 2: every block redundantly computes the fc2 head (g_p is hot in L2),
// then block b sums rows [ws,we] for columns 4b..4b+3.
//  - tid 0 computes sigmoid's exp -> p_t -> window bounds.
//  - thread 64 (different warp) computes e_t's exp AFTER p_t is published,
//    overlapping it with the hs window loads issued by all threads.
//  - each thread: <=3 independent predicated loads (single latency batch).
// ---------------------------------------------------------------------------
__global__ void __launch_bounds__(256) windowsum_kernel(
        const float* __restrict__ hs,
        const float* __restrict__ fc2_w,
        const float* __restrict__ fc2_b,
        float* __restrict__ out, int S) {
    const int tid  = threadIdx.x;
    const int lane = tid & 31;
    const int wid  = tid >> 5;

    __shared__ double sred[8];
    __shared__ double sh_pt;
    __shared__ int    sh_ws, sh_we;
    __shared__ float  sh_et;
    __shared__ float  colsum[256];

    // fc2 dot: one term per thread, warp reduce, then 8 partials
    {
        double term = (double)__ldcg(&g_p[tid]) * (double)fc2_w[tid];
        #pragma unroll
        for (int o = 16; o > 0; o >>= 1)
            term += __shfl_down_sync(0xffffffffu, term, o);
        if (lane == 0) sred[wid] = term;
    }
    __syncthreads();

    if (tid == 0) {
        double z = ((sred[0] + sred[1]) + (sred[2] + sred[3]))
                 + ((sred[4] + sred[5]) + (sred[6] + sred[7]))
                 + (double)fc2_b[0];
        double pt = (double)S / (1.0 + exp(-z));        // fp64 exp #1
        double wsd = ceil(pt - (double)WINDOW);
        if (wsd < 0.0) wsd = 0.0;
        double wed = floor(pt + (double)WINDOW);
        if (wed > (double)(S - 1)) wed = (double)(S - 1);
        sh_pt = pt;
        sh_ws = (int)wsd;
        sh_we = (int)wed;
    }
    __syncthreads();

    const int ws = sh_ws;
    const int we = sh_we;

    // issue the window loads immediately (single batch, predicated)
    const int col    = (blockIdx.x << 2) + (tid & 3);
    const int rowoff = tid >> 2;                        // 0..63
    const float* base = hs + col;
    const int r0 = ws + rowoff;                         // 3 slots cover <=192 rows

    float a = 0.f, b = 0.f, c = 0.f;
    if (r0       <= we) a = base[(size_t)(r0)       * HIDDEN];
    if (r0 + 64  <= we) b = base[(size_t)(r0 + 64)  * HIDDEN];
    if (r0 + 128 <= we) c = base[(size_t)(r0 + 128) * HIDDEN];

    // e_t's exp on a different warp -> overlaps the loads above
    if (tid == 64)                                       // fp64 exp #2
        sh_et = (float)exp(((double)S - sh_pt) / 2048.0);

    colsum[tid] = (a + b) + c;
    __syncthreads();

    // tree reduce over the 64 row-groups (stride multiples of 4 keep columns)
    if (tid < 128) colsum[tid] += colsum[tid + 128];
    __syncthreads();
    if (tid < 64)  colsum[tid] += colsum[tid + 64];
    __syncthreads();
    if (tid < 32) {
        colsum[tid] += colsum[tid + 32];
        __syncwarp(0xffffffffu);
        if (tid < 16) colsum[tid] += colsum[tid + 16];
        __syncwarp(0xffffffffu);
        if (tid < 8)  colsum[tid] += colsum[tid + 8];
        __syncwarp(0xffffffffu);
        if (tid < 4)
            out[col] = sh_et * (colsum[tid] + colsum[tid + 4]);
    }
}

extern "C" void kernel_launch(void* const* d_in, const int* in_sizes, int n_in,
                              void* d_out, int out_size) {
    const float* hs    = (const float*)d_in[0];
    const float* ht    = (const float*)d_in[1];
    const float* fc1_w = (const float*)d_in[2];
    const float* fc1_b = (const float*)d_in[3];
    const float* fc2_w = (const float*)d_in[4];
    const float* fc2_b = (const float*)d_in[5];

    const int S = in_sizes[0] / HIDDEN;   // host-side constant, capture-safe

    mlp1_kernel<<<32, 256>>>(ht, fc1_w, fc1_b);
    windowsum_kernel<<<NINTER, 256>>>(hs, fc2_w, fc2_b, (float*)d_out, S);
}

// round 4
// speedup vs baseline: 1.4812x; 1.4812x over previous
#include <cuda_runtime.h>
#include <math.h>

#define HIDDEN 1024
#define NINTER 256
#define WINDOW 64

// scratch (allocation-free rule: __device__ global)
__device__ float g_p[NINTER];

// ---------------------------------------------------------------------------
// Fast fp64 exp, rel err ~1e-13 (degree-9 Taylor after range reduction).
// ~11 dependent DFMA + exact 2^n scale; NO library calls, no fp64 divide.
// Valid for |x| < ~700 (here |x| < ~40).
// ---------------------------------------------------------------------------
__device__ __forceinline__ double fast_exp(double x) {
    const double LOG2E  = 1.4426950408889634074;
    const double LN2_HI = 6.9314718055994528623e-1;
    const double LN2_LO = 2.3190468138462995584e-17;
    double n = rint(x * LOG2E);
    double r = fma(-n, LN2_HI, x);
    r = fma(-n, LN2_LO, r);
    double p = 2.7557319223985890653e-6;            // 1/9!
    p = fma(p, r, 2.4801587301587301566e-5);        // 1/8!
    p = fma(p, r, 1.9841269841269841253e-4);        // 1/7!
    p = fma(p, r, 1.3888888888888889419e-3);        // 1/6!
    p = fma(p, r, 8.3333333333333332177e-3);        // 1/5!
    p = fma(p, r, 4.1666666666666664354e-2);        // 1/4!
    p = fma(p, r, 1.6666666666666665741e-1);        // 1/3!
    p = fma(p, r, 5.0e-1);                          // 1/2!
    p = fma(p, r, 1.0);
    p = fma(p, r, 1.0);
    long long ni = (long long)n;
    double sc = __longlong_as_double((ni + 1023LL) << 52);   // exact 2^n
    return p * sc;
}

// 1/d to full fp64 via fp32 rcp seed + 2 Newton iterations (no DDIV chain)
__device__ __forceinline__ double fast_recip(double d) {
    double y = (double)__frcp_rn((float)d);
    y = y * fma(-d, y, 2.0);
    y = y * fma(-d, y, 2.0);
    return y;
}

// ---------------------------------------------------------------------------
// Kernel 1: g_p[row] = tanhf(dot_fp64(fc1_w[row,:], h_t) + fc1_b[row])
// Block-per-row, 256 blocks x 256 threads; each thread one float4 of w and h.
// ---------------------------------------------------------------------------
__global__ void __launch_bounds__(256) mlp1_kernel(
        const float* __restrict__ ht,
        const float* __restrict__ fc1_w,
        const float* __restrict__ fc1_b) {
    const int tid  = threadIdx.x;
    const int lane = tid & 31;
    const int wid  = tid >> 5;

    float4 w = ((const float4*)(fc1_w + (size_t)blockIdx.x * HIDDEN))[tid];
    float4 h = ((const float4*)ht)[tid];
    double acc = (double)w.x * h.x + (double)w.y * h.y
               + (double)w.z * h.z + (double)w.w * h.w;

    #pragma unroll
    for (int o = 16; o > 0; o >>= 1)
        acc += __shfl_down_sync(0xffffffffu, acc, o);

    __shared__ double s[8];
    if (lane == 0) s[wid] = acc;
    __syncthreads();
    if (tid == 0) {
        double z = ((s[0] + s[1]) + (s[2] + s[3]))
                 + ((s[4] + s[5]) + (s[6] + s[7]))
                 + (double)fc1_b[blockIdx.x];
        g_p[blockIdx.x] = tanhf((float)z);          // fp32 tanh: ~1e-7 abs
    }
}

// ---------------------------------------------------------------------------
// Kernel 2: every block redundantly computes the fc2 head (g_p hot in L2),
// then block b sums rows [ws,we] for columns 4b..4b+3 (<=3 predicated
// independent loads per thread = one DRAM-latency batch).
// ---------------------------------------------------------------------------
__global__ void __launch_bounds__(256) windowsum_kernel(
        const float* __restrict__ hs,
        const float* __restrict__ fc2_w,
        const float* __restrict__ fc2_b,
        float* __restrict__ out, int S) {
    const int tid  = threadIdx.x;
    const int lane = tid & 31;
    const int wid  = tid >> 5;

    __shared__ double sred[8];
    __shared__ int    sh_ws, sh_we;
    __shared__ float  sh_et;
    __shared__ float  colsum[256];

    // fc2 dot: one term per thread
    {
        double term = (double)__ldcg(&g_p[tid]) * (double)fc2_w[tid];
        #pragma unroll
        for (int o = 16; o > 0; o >>= 1)
            term += __shfl_down_sync(0xffffffffu, term, o);
        if (lane == 0) sred[wid] = term;
    }
    __syncthreads();

    if (tid == 0) {
        double z = ((sred[0] + sred[1]) + (sred[2] + sred[3]))
                 + ((sred[4] + sred[5]) + (sred[6] + sred[7]))
                 + (double)fc2_b[0];
        double e  = fast_exp(-z);                       // ~550 cyc
        double pt = (double)S * fast_recip(1.0 + e);    // ~150 cyc
        double wsd = ceil(pt - (double)WINDOW);
        if (wsd < 0.0) wsd = 0.0;
        double wed = floor(pt + (double)WINDOW);
        if (wed > (double)(S - 1)) wed = (double)(S - 1);
        sh_ws = (int)wsd;
        sh_we = (int)wed;
        sh_et = expf((float)(((double)S - pt) * (1.0 / 2048.0)));
    }
    __syncthreads();

    const int ws = sh_ws;
    const int we = sh_we;

    const int col    = (blockIdx.x << 2) + (tid & 3);
    const int rowoff = tid >> 2;                        // 0..63
    const float* base = hs + col;
    const int r0 = ws + rowoff;                         // 3 slots cover <=192 rows

    float a = 0.f, b = 0.f, c = 0.f;
    if (r0       <= we) a = base[(size_t)(r0)       * HIDDEN];
    if (r0 + 64  <= we) b = base[(size_t)(r0 + 64)  * HIDDEN];
    if (r0 + 128 <= we) c = base[(size_t)(r0 + 128) * HIDDEN];
    colsum[tid] = (a + b) + c;
    __syncthreads();

    // tree reduce over 64 row-groups (strides keep column lanes aligned)
    if (tid < 128) colsum[tid] += colsum[tid + 128];
    __syncthreads();
    if (tid < 64)  colsum[tid] += colsum[tid + 64];
    __syncthreads();
    if (tid < 32) {
        colsum[tid] += colsum[tid + 32];
        __syncwarp(0xffffffffu);
        if (tid < 16) colsum[tid] += colsum[tid + 16];
        __syncwarp(0xffffffffu);
        if (tid < 8)  colsum[tid] += colsum[tid + 8];
        __syncwarp(0xffffffffu);
        if (tid < 4)
            out[col] = sh_et * (colsum[tid] + colsum[tid + 4]);
    }
}

extern "C" void kernel_launch(void* const* d_in, const int* in_sizes, int n_in,
                              void* d_out, int out_size) {
    const float* hs    = (const float*)d_in[0];
    const float* ht    = (const float*)d_in[1];
    const float* fc1_w = (const float*)d_in[2];
    const float* fc1_b = (const float*)d_in[3];
    const float* fc2_w = (const float*)d_in[4];
    const float* fc2_b = (const float*)d_in[5];

    const int S = in_sizes[0] / HIDDEN;   // host-side constant, capture-safe

    mlp1_kernel<<<NINTER, 256>>>(ht, fc1_w, fc1_b);
    windowsum_kernel<<<NINTER, 256>>>(hs, fc2_w, fc2_b, (float*)d_out, S);
}